// round 6
// baseline (speedup 1.0000x reference)
#include <cuda_runtime.h>
#include <cstdint>

#define NB   2048
#define INS  512
#define SEQL 128
#define NH   12
#define NOUT 3
#define BPB  4   // batches per block in pre_kernel (1 warp per batch)

// scratch (allocation-free contract: __device__ globals)
__device__ float g_pre[(size_t)SEQL * NB * NH];   // [s][b][h]  ~12.6 MB
__device__ float g_hbwd[NB * NH];

__device__ __forceinline__ unsigned long long fma2(unsigned long long a,
                                                   unsigned long long b,
                                                   unsigned long long c) {
    unsigned long long d;
    asm("fma.rn.f32x2 %0, %1, %2, %3;" : "=l"(d) : "l"(a), "l"(b), "l"(c));
    return d;
}
__device__ __forceinline__ unsigned long long pk2(float f) {
    unsigned long long u;
    asm("mov.b64 %0, {%1, %1};" : "=l"(u) : "f"(f));
    return u;
}
__device__ __forceinline__ float ftanh(float x) {
    float e = __expf(2.0f * x);
    return 1.0f - __fdividef(2.0f, e + 1.0f);
}

// ---------------------------------------------------------------------------
// Kernel 1: pre[s,b,h] = sum_i emb[x[b,i], s] * w_ih_f[h,i]
// ONE warp covers a full batch (all 128 s): lane owns s in
// {2l, 2l+1, 64+2l, 64+2l+1}. This amortizes the 3 broadcast weight-LDS.128
// and index-LDS over 24 FFMA2 (vs 12 in R5) cutting L1tex wavefronts/i by 31%
// (L1 was 71.8% = co-binding). acc = 24 f32x2 (48 regs); ping-pong 4-i
// e-prefetch; __launch_bounds__(128,5) caps regs at 102.
// ---------------------------------------------------------------------------
extern "C" __global__ void __launch_bounds__(128, 5)
pre_kernel(const int* __restrict__ x, const float* __restrict__ emb,
           const float* __restrict__ wih) {
    __shared__ float2 w2[INS * 6];   // 24 KB: w2[i*6+k] = (w[2k,i], w[2k+1,i])
    __shared__ int    xs[BPB * INS]; // 8 KB

    const int tid = threadIdx.x;
    const int b0 = blockIdx.x * BPB;

    for (int t = tid; t < INS * 6; t += 128) {
        int i = t & (INS - 1);
        int k = t >> 9;              // 0..5
        w2[i * 6 + k] = make_float2(wih[(2 * k) * INS + i],
                                    wih[(2 * k + 1) * INS + i]);
    }
    for (int t = tid; t < BPB * INS; t += 128)
        xs[t] = x[(size_t)b0 * INS + t];
    __syncthreads();

    const int warp = tid >> 5;
    const int lane = tid & 31;
    const int b = b0 + warp;
    const int* xrow = xs + warp * INS;
    const float* eL = emb + 2 * lane;        // s = 2l, 2l+1
    const float* eH = emb + 64 + 2 * lane;   // s = 64+2l, 64+2l+1

    // acc[s-slot][k]: slot 0: s=2l, 1: s=2l+1, 2: s=64+2l, 3: s=64+2l+1
    unsigned long long aa[4][6];
#pragma unroll
    for (int sp = 0; sp < 4; sp++)
#pragma unroll
        for (int k = 0; k < 6; k++) aa[sp][k] = 0ull;

    float2 bufA[8], bufB[8];   // [2*u]=eL, [2*u+1]=eH for u in 0..3

#define LOADE(buf, base_i)                                                    \
    do {                                                                      \
        int4 q = *(const int4*)(xrow + (base_i));                             \
        buf[0] = *(const float2*)(eL + (size_t)q.x * SEQL);                  \
        buf[1] = *(const float2*)(eH + (size_t)q.x * SEQL);                  \
        buf[2] = *(const float2*)(eL + (size_t)q.y * SEQL);                  \
        buf[3] = *(const float2*)(eH + (size_t)q.y * SEQL);                  \
        buf[4] = *(const float2*)(eL + (size_t)q.z * SEQL);                  \
        buf[5] = *(const float2*)(eH + (size_t)q.z * SEQL);                  \
        buf[6] = *(const float2*)(eL + (size_t)q.w * SEQL);                  \
        buf[7] = *(const float2*)(eH + (size_t)q.w * SEQL);                  \
    } while (0)

#define COMPUTE4(buf, base_i)                                                 \
    do {                                                                      \
        _Pragma("unroll")                                                     \
        for (int u = 0; u < 4; u++) {                                         \
            unsigned long long pa = pk2(buf[2 * u].x);                        \
            unsigned long long pb = pk2(buf[2 * u].y);                        \
            unsigned long long pc = pk2(buf[2 * u + 1].x);                    \
            unsigned long long pd = pk2(buf[2 * u + 1].y);                    \
            const ulonglong2* wv =                                            \
                (const ulonglong2*)(w2 + (size_t)((base_i) + u) * 6);         \
            ulonglong2 wA = wv[0], wB = wv[1], wC = wv[2];                    \
            aa[0][0] = fma2(pa, wA.x, aa[0][0]);                              \
            aa[1][0] = fma2(pb, wA.x, aa[1][0]);                              \
            aa[2][0] = fma2(pc, wA.x, aa[2][0]);                              \
            aa[3][0] = fma2(pd, wA.x, aa[3][0]);                              \
            aa[0][1] = fma2(pa, wA.y, aa[0][1]);                              \
            aa[1][1] = fma2(pb, wA.y, aa[1][1]);                              \
            aa[2][1] = fma2(pc, wA.y, aa[2][1]);                              \
            aa[3][1] = fma2(pd, wA.y, aa[3][1]);                              \
            aa[0][2] = fma2(pa, wB.x, aa[0][2]);                              \
            aa[1][2] = fma2(pb, wB.x, aa[1][2]);                              \
            aa[2][2] = fma2(pc, wB.x, aa[2][2]);                              \
            aa[3][2] = fma2(pd, wB.x, aa[3][2]);                              \
            aa[0][3] = fma2(pa, wB.y, aa[0][3]);                              \
            aa[1][3] = fma2(pb, wB.y, aa[1][3]);                              \
            aa[2][3] = fma2(pc, wB.y, aa[2][3]);                              \
            aa[3][3] = fma2(pd, wB.y, aa[3][3]);                              \
            aa[0][4] = fma2(pa, wC.x, aa[0][4]);                              \
            aa[1][4] = fma2(pb, wC.x, aa[1][4]);                              \
            aa[2][4] = fma2(pc, wC.x, aa[2][4]);                              \
            aa[3][4] = fma2(pd, wC.x, aa[3][4]);                              \
            aa[0][5] = fma2(pa, wC.y, aa[0][5]);                              \
            aa[1][5] = fma2(pb, wC.y, aa[1][5]);                              \
            aa[2][5] = fma2(pc, wC.y, aa[2][5]);                              \
            aa[3][5] = fma2(pd, wC.y, aa[3][5]);                              \
        }                                                                     \
    } while (0)

    LOADE(bufA, 0);

#pragma unroll 1
    for (int i0 = 0; i0 < INS; i0 += 8) {
        LOADE(bufB, i0 + 4);                        // next 4 i in flight
        COMPUTE4(bufA, i0);
        LOADE(bufA, (i0 + 8 < INS) ? (i0 + 8) : 0); // next chunk (tail clamp)
        COMPUTE4(bufB, i0 + 4);
    }
#undef LOADE
#undef COMPUTE4

    // write 4 s-rows of 12 contiguous floats each
    const int sv[4] = {2 * lane, 2 * lane + 1, 64 + 2 * lane, 64 + 2 * lane + 1};
#pragma unroll
    for (int sp = 0; sp < 4; sp++) {
        ulonglong2* d =
            (ulonglong2*)(g_pre + ((size_t)sv[sp] * NB + b) * NH);
        ulonglong2 v0, v1, v2;
        v0.x = aa[sp][0]; v0.y = aa[sp][1];
        v1.x = aa[sp][2]; v1.y = aa[sp][3];
        v2.x = aa[sp][4]; v2.y = aa[sp][5];
        d[0] = v0; d[1] = v1; d[2] = v2;
    }
}

// ---------------------------------------------------------------------------
// Kernel 2: h_bwd — warp per batch, MLP=16 prefetch.
// ---------------------------------------------------------------------------
extern "C" __global__ void __launch_bounds__(256)
bwd_kernel(const int* __restrict__ x, const float* __restrict__ emb,
           const float* __restrict__ wir, const float* __restrict__ bir,
           const float* __restrict__ bhr) {
    __shared__ float ws[NH * INS];   // 24 KB
    const int tid = threadIdx.x;
    for (int t = tid; t < NH * INS; t += 256) ws[t] = wir[t];
    __syncthreads();

    const int warp = tid >> 5, lane = tid & 31;
    const int b = blockIdx.x * 8 + warp;

    int idxv[16];
#pragma unroll
    for (int j = 0; j < 16; j++)
        idxv[j] = x[(size_t)b * INS + lane + 32 * j];
    float ev[16];
#pragma unroll
    for (int j = 0; j < 16; j++)
        ev[j] = emb[(size_t)idxv[j] * SEQL + (SEQL - 1)];

    float p[NH];
#pragma unroll
    for (int h = 0; h < NH; h++) p[h] = 0.f;
#pragma unroll
    for (int j = 0; j < 16; j++) {
        const int i = lane + 32 * j;
#pragma unroll
        for (int h = 0; h < NH; h++) p[h] = fmaf(ev[j], ws[h * INS + i], p[h]);
    }
#pragma unroll
    for (int h = 0; h < NH; h++) {
        float v = p[h];
#pragma unroll
        for (int o = 16; o; o >>= 1) v += __shfl_xor_sync(0xffffffffu, v, o);
        p[h] = v;
    }
    if (lane == 0) {
        float r[NH];
#pragma unroll
        for (int h = 0; h < NH; h++) r[h] = ftanh(p[h] + bir[h] + bhr[h]);
        float4* d = (float4*)(g_hbwd + (size_t)b * NH);
        d[0] = make_float4(r[0], r[1], r[2], r[3]);
        d[1] = make_float4(r[4], r[5], r[6], r[7]);
        d[2] = make_float4(r[8], r[9], r[10], r[11]);
    }
}

// ---------------------------------------------------------------------------
// Kernel 3: forward scan + fused FC epilogue.
// Single chain per thread (R5's 2-chain halved the grid below 148 SMs and
// regressed). 128 thr = 8 batches per block -> 256 blocks fills the chip.
// Depth-3 rolling prefetch hides the ~250cyc L2 load of pre[s+3].
// ---------------------------------------------------------------------------
extern "C" __global__ void __launch_bounds__(128)
scan_kernel(const float* __restrict__ whh, const float* __restrict__ bih,
            const float* __restrict__ bhh, const float* __restrict__ fcw,
            const float* __restrict__ fcb, float* __restrict__ out) {
    const int tid = threadIdx.x;
    const int b = blockIdx.x * 8 + (tid >> 4);
    const int hl = tid & 15;
    const int hc = hl < NH ? hl : 0;

    float wrow[NH];
#pragma unroll
    for (int j = 0; j < NH; j++) wrow[j] = whh[hc * NH + j];
    const float bias = bih[hc] + bhh[hc];

    const float* ps = g_pre + (size_t)b * NH + hc;
    const size_t sstr = (size_t)NB * NH;

    float h = 0.f;
    float p0 = ps[0], p1 = ps[sstr], p2 = ps[2 * sstr];

    for (int s = 0; s < SEQL; s++) {
        float p = p0;
        p0 = p1; p1 = p2;
        int sl = (s + 3 < SEQL) ? (s + 3) : 0;
        p2 = ps[(size_t)sl * sstr];

        float v[NH];
#pragma unroll
        for (int j = 0; j < NH; j++) v[j] = __shfl_sync(0xffffffffu, h, j, 16);
        float t0 = fmaf(v[0], wrow[0], p + bias);
        float t1 = v[1] * wrow[1];
        float t2 = v[2] * wrow[2];
#pragma unroll
        for (int j = 3; j < NH; j += 3) {
            t0 = fmaf(v[j    ], wrow[j    ], t0);
            t1 = fmaf(v[j + 1], wrow[j + 1], t1);
            t2 = fmaf(v[j + 2], wrow[j + 2], t2);
        }
        h = ftanh(t0 + t1 + t2);
    }

    float v[NH];
#pragma unroll
    for (int j = 0; j < NH; j++) v[j] = __shfl_sync(0xffffffffu, h, j, 16);
    if (hl < NOUT) {
        float o = fcb[hl];
        const float* hb = g_hbwd + (size_t)b * NH;
#pragma unroll
        for (int j = 0; j < NH; j++) o = fmaf(v[j], fcw[hl * 2 * NH + j], o);
#pragma unroll
        for (int j = 0; j < NH; j++) o = fmaf(hb[j], fcw[hl * 2 * NH + NH + j], o);
        out[b * NOUT + hl] = o;
    }
}

// ---------------------------------------------------------------------------
extern "C" void kernel_launch(void* const* d_in, const int* in_sizes, int n_in,
                              void* d_out, int out_size) {
    const int*   x      = (const int*)  d_in[0];
    const float* emb    = (const float*)d_in[1];
    const float* w_ih_f = (const float*)d_in[2];
    const float* w_hh_f = (const float*)d_in[3];
    const float* b_ih_f = (const float*)d_in[4];
    const float* b_hh_f = (const float*)d_in[5];
    const float* w_ih_r = (const float*)d_in[6];
    // d_in[7] = w_hh_r (unused: reference consumes only the one-step reverse state)
    const float* b_ih_r = (const float*)d_in[8];
    const float* b_hh_r = (const float*)d_in[9];
    const float* fc_w   = (const float*)d_in[10];
    const float* fc_b   = (const float*)d_in[11];
    float* out = (float*)d_out;

    pre_kernel<<<NB / BPB, 128>>>(x, emb, w_ih_f);
    bwd_kernel<<<NB / 8, 256>>>(x, emb, w_ih_r, b_ih_r, b_hh_r);
    scan_kernel<<<NB / 8, 128>>>(w_hh_f, b_ih_f, b_hh_f, fc_w, fc_b, out);
}